// round 12
// baseline (speedup 1.0000x reference)
#include <cuda_runtime.h>
#include <cstdint>

#define IMG_S 128
#define NPIX (IMG_S * IMG_S)
#define MAXF 4096
#define Z_NEAR 0.1f
#define Z_FAR 100.0f

#define RB 32            // epilogue blocks: 32 x 256 threads x 2 px == NPIX

// ---- scratch (zero-initialized at module load; resolve restores zeros) ----
__device__ __align__(16) unsigned long long g_zbuf[NPIX];  // 0 == empty
__device__ float4 g_colors[MAXF];
__device__ int g_maxbits;             // gray max bits (idempotent across replays)
__device__ float g_slot_g2[RB];
__device__ float g_slot_gm[RB];
__device__ float g_slot_m2[RB];
__device__ float g_slot_msk[RB];
__device__ unsigned int g_ticket;

// ---------------------------------------------------------------------------
__device__ __forceinline__ float3 project_vert(float3 p,
                                               const float* __restrict__ R,
                                               const float* __restrict__ t,
                                               const float* __restrict__ K) {
    float vx = R[0] * p.x + R[1] * p.y + R[2] * p.z + t[0];
    float vy = R[3] * p.x + R[4] * p.y + R[5] * p.z + t[1];
    float vz = R[6] * p.x + R[7] * p.y + R[8] * p.z + t[2];
    float zd = vz + 1e-9f;
    float xn = vx / zd;
    float yn = vy / zd;
    float u = K[0] * xn + K[1] * yn + K[2];
    float v = K[3] * xn + K[4] * yn + K[5];
    float S = (float)IMG_S;
    float uu  = 2.0f * (u - S * 0.5f) / S;
    float vfl = S - v;
    float vvn = 2.0f * (vfl - S * 0.5f) / S;
    return make_float3(uu, vvn, vz);
}

// 8-lane subgroup per face: 4 faces per warp. Setup issues once per warp
// (serving 4 faces) -> 4x fewer setup/MUFU instructions than warp-per-face.
__global__ void k_raster(const float* __restrict__ verts,
                         const int*   __restrict__ faces,
                         const float* __restrict__ tex,
                         const float* __restrict__ R,
                         const float* __restrict__ t,
                         const float* __restrict__ K,
                         const float* __restrict__ Ldir,
                         const float* __restrict__ idir_p,
                         const float* __restrict__ iamb_p,
                         int F) {
    int wid  = (blockIdx.x * blockDim.x + threadIdx.x) >> 5;
    int lane = threadIdx.x & 31;
    int sub  = lane >> 3;            // subgroup 0..3
    int sl   = lane & 7;             // lane within subgroup
    int f    = wid * 4 + sub;

    bool active = (f < F);
    int total = 0;
    int x0 = 0, y0 = 0, bw = 1;
    float e0x = 0, e0y = 0, e1x = 0, e1y = 0, e2x = 0, e2y = 0;
    float a0x = 0, a0y = 0, a1x = 0, a1y = 0, a2x = 0, a2y = 0;
    float rz0 = 0, rz1 = 0, rz2 = 0;

    if (active) {
        int i0 = faces[3 * f + 0];
        int i1 = faces[3 * f + 1];
        int i2 = faces[3 * f + 2];

        float3 A = make_float3(verts[3 * i0], verts[3 * i0 + 1], verts[3 * i0 + 2]);
        float3 B = make_float3(verts[3 * i1], verts[3 * i1 + 1], verts[3 * i1 + 2]);
        float3 C = make_float3(verts[3 * i2], verts[3 * i2 + 1], verts[3 * i2 + 2]);

        // ---- lighting (world space) ----
        float3 v10 = make_float3(A.x - B.x, A.y - B.y, A.z - B.z);
        float3 v12 = make_float3(C.x - B.x, C.y - B.y, C.z - B.z);
        float nx = v10.y * v12.z - v10.z * v12.y;
        float ny = v10.z * v12.x - v10.x * v12.z;
        float nz = v10.x * v12.y - v10.y * v12.x;
        float nrm = sqrtf(nx * nx + ny * ny + nz * nz);
        float inv = 1.0f / fmaxf(nrm, 1e-5f);
        nx *= inv; ny *= inv; nz *= inv;
        float cosv = fmaxf(0.0f, nx * Ldir[0] + ny * Ldir[1] + nz * Ldir[2]);
        float light = iamb_p[0] + idir_p[0] * cosv;
        if (sl == 0) {
            g_colors[f] = make_float4(tex[3 * f + 0] * light,
                                      tex[3 * f + 1] * light,
                                      tex[3 * f + 2] * light, 0.0f);
        }

        // ---- projection (exact reference algebra) ----
        float3 p0 = project_vert(A, R, t, K);
        float3 p1 = project_vert(B, R, t, K);
        float3 p2 = project_vert(C, R, t, K);

        rz0 = 1.0f / p0.z;
        rz1 = 1.0f / p1.z;
        rz2 = 1.0f / p2.z;

        // ---- bbox in pixel space ----
        float Sf = (float)IMG_S;
        float minu = fminf(fminf(p0.x, p1.x), p2.x);
        float maxu = fmaxf(fmaxf(p0.x, p1.x), p2.x);
        float minv = fminf(fminf(p0.y, p1.y), p2.y);
        float maxv = fmaxf(fmaxf(p0.y, p1.y), p2.y);
        int xa = max(0,         (int)floorf((minu * Sf + Sf - 1.0f) * 0.5f));
        int xb = min(IMG_S - 1, (int)ceilf ((maxu * Sf + Sf - 1.0f) * 0.5f));
        int ya = max(0,         (int)floorf((minv * Sf + Sf - 1.0f) * 0.5f));
        int yb = min(IMG_S - 1, (int)ceilf ((maxv * Sf + Sf - 1.0f) * 0.5f));
        if (xa <= xb && ya <= yb) {
            x0 = xa; y0 = ya;
            bw = xb - xa + 1;
            total = bw * (yb - ya + 1);
        }

        e0x = p2.x - p1.x; e0y = p2.y - p1.y; a0x = p1.x; a0y = p1.y;  // edge(v1,v2)
        e1x = p0.x - p2.x; e1y = p0.y - p2.y; a1x = p2.x; a1y = p2.y;  // edge(v2,v0)
        e2x = p1.x - p0.x; e2y = p1.y - p0.y; a2x = p0.x; a2y = p0.y;  // edge(v0,v1)
    }

    const float Sf = (float)IMG_S;
    for (int i = sl; i < total; i += 8) {
        int x = x0 + (i % bw);
        int y = y0 + (i / bw);
        float px = (2.0f * x + 1.0f - Sf) / Sf;
        float py = (2.0f * y + 1.0f - Sf) / Sf;

        // exact reference algebra for the sign tests
        float w0 = e0x * (py - a0y) - e0y * (px - a0x);
        float w1 = e1x * (py - a1y) - e1y * (px - a1x);
        float w2 = e2x * (py - a2y) - e2y * (px - a2x);
        float area = w0 + w1 + w2;
        bool ok = fabsf(area) > 1e-10f;
        bool ins = ((w0 >= 0.0f && w1 >= 0.0f && w2 >= 0.0f) ||
                    (w0 <= 0.0f && w1 <= 0.0f && w2 <= 0.0f)) && ok;
        if (!ins) continue;
        // zp = area / (w0*rz0 + w1*rz1 + w2*rz2): single division; equals
        // reference 1/(sum (w_i*ia)*rz_i + 1e-12) up to ~1ulp reassoc + 8e-12.
        float num = w0 * rz0 + w1 * rz1 + w2 * rz2;
        float zp = area / num;
        if (zp > Z_NEAR && zp < Z_FAR) {
            // inverted key: atomicMax == lexicographic min of (z_bits, f)
            // == argmin with first-index tie-break. empty == 0.
            unsigned long long key =
                ((unsigned long long)(~__float_as_uint(zp)) << 32) |
                (unsigned long long)(~(unsigned int)f);
            atomicMax(&g_zbuf[y * IMG_S + x], key);
        }
    }
}

// ---------------------------------------------------------------------------
// Single-pass fused epilogue, 2 pixels per thread (vector zbuf load; scalar
// RGB stores -- out data begins at index 1 so vector stores are misaligned).
// Loss via algebraic expansion (no maxv needed in partials).
__global__ void __launch_bounds__(256)
k_resolve_loss(float* __restrict__ out,
               const float* __restrict__ mimg,
               const float* __restrict__ mask) {
    const int tid  = threadIdx.x;
    const int lane = tid & 31;
    const int wrp  = tid >> 5;
    const int q    = blockIdx.x * 256 + tid;     // pair index; RB*256*2 == NPIX
    const int p    = q * 2;

    // ---- resolve 2 pixels ----
    ulonglong2 kk = *((const ulonglong2*)&g_zbuf[p]);
    float r0 = 0, g0 = 0, b0 = 0, r1 = 0, g1 = 0, b1 = 0;
    if (kk.x != 0ull) {
        int f = (int)(~(unsigned int)(kk.x & 0xFFFFFFFFull));
        float4 c = g_colors[f];
        r0 = c.x; g0 = c.y; b0 = c.z;
    }
    if (kk.y != 0ull) {
        int f = (int)(~(unsigned int)(kk.y & 0xFFFFFFFFull));
        float4 c = g_colors[f];
        r1 = c.x; g1 = c.y; b1 = c.z;
    }
    if ((kk.x | kk.y) != 0ull)
        *((ulonglong2*)&g_zbuf[p]) = make_ulonglong2(0ull, 0ull); // restore empty

    out[1 + 0 * NPIX + p]     = r0;
    out[1 + 0 * NPIX + p + 1] = r1;
    out[1 + 1 * NPIX + p]     = g0;
    out[1 + 1 * NPIX + p + 1] = g1;
    out[1 + 2 * NPIX + p]     = b0;
    out[1 + 2 * NPIX + p + 1] = b1;

    float gray0 = r0 + g0 + b0;
    float gray1 = r1 + g1 + b1;
    float2 mm    = *((const float2*)&mimg[p]);
    float2 kmask = *((const float2*)&mask[p]);

    // ---- block reductions: max, g^2, g*m, m^2, mask ----
    float mx = fmaxf(gray0, gray1);
    float g2 = gray0 * gray0 + gray1 * gray1;
    float gm = gray0 * mm.x + gray1 * mm.y;
    float m2 = mm.x * mm.x + mm.y * mm.y;
    float mk = kmask.x + kmask.y;
    #pragma unroll
    for (int o = 16; o > 0; o >>= 1) {
        mx = fmaxf(mx, __shfl_down_sync(0xFFFFFFFFu, mx, o));
        g2 += __shfl_down_sync(0xFFFFFFFFu, g2, o);
        gm += __shfl_down_sync(0xFFFFFFFFu, gm, o);
        m2 += __shfl_down_sync(0xFFFFFFFFu, m2, o);
        mk += __shfl_down_sync(0xFFFFFFFFu, mk, o);
    }
    __shared__ float smx[8], sg2[8], sgm[8], sm2[8], smk[8];
    if (lane == 0) { smx[wrp] = mx; sg2[wrp] = g2; sgm[wrp] = gm;
                     sm2[wrp] = m2; smk[wrp] = mk; }
    __syncthreads();
    if (tid == 0) {
        float a = smx[0], s2 = sg2[0], sm = sgm[0], s3 = sm2[0], s4 = smk[0];
        #pragma unroll
        for (int w = 1; w < 8; w++) {
            a  = fmaxf(a, smx[w]);
            s2 += sg2[w]; sm += sgm[w]; s3 += sm2[w]; s4 += smk[w];
        }
        atomicMax(&g_maxbits, __float_as_int(a));
        g_slot_g2[blockIdx.x]  = s2;
        g_slot_gm[blockIdx.x]  = sm;
        g_slot_m2[blockIdx.x]  = s3;
        g_slot_msk[blockIdx.x] = s4;
        __threadfence();
        unsigned int tkt = atomicAdd(&g_ticket, 1u);
        if (tkt == RB - 1) {
            g_ticket = 0;                        // reset for next replay
            float A = g_slot_g2[0], Bq = g_slot_gm[0];
            float C = g_slot_m2[0], M = g_slot_msk[0];
            #pragma unroll
            for (int w = 1; w < RB; w++) {
                A += g_slot_g2[w]; Bq += g_slot_gm[w];
                C += g_slot_m2[w]; M  += g_slot_msk[w];
            }
            float maxv = __int_as_float(g_maxbits);
            float S1 = A / (maxv * maxv) - 2.0f * Bq / maxv + C;
            out[0] = S1 / M;
        }
    }
}

// ---------------------------------------------------------------------------
extern "C" void kernel_launch(void* const* d_in, const int* in_sizes, int n_in,
                              void* d_out, int out_size) {
    const float* verts = (const float*)d_in[0];
    const int*   faces = (const int*)  d_in[1];
    const float* tex   = (const float*)d_in[2];
    const float* R     = (const float*)d_in[3];
    const float* t     = (const float*)d_in[4];
    const float* K     = (const float*)d_in[5];
    const float* mimg  = (const float*)d_in[6];
    const float* mask  = (const float*)d_in[7];
    const float* Ldir  = (const float*)d_in[8];
    const float* idir  = (const float*)d_in[9];
    const float* iamb  = (const float*)d_in[10];
    float* out = (float*)d_out;

    int F = in_sizes[1] / 3;

    // 4 faces per warp (8-lane subgroups); 128 threads = 16 faces per block
    int blocks = (F + 15) / 16;
    k_raster<<<blocks, 128>>>(verts, faces, tex, R, t, K, Ldir, idir, iamb, F);
    k_resolve_loss<<<RB, 256>>>(out, mimg, mask);
}

// round 14
// speedup vs baseline: 2.1707x; 2.1707x over previous
#include <cuda_runtime.h>
#include <cstdint>

#define IMG_S 128
#define NPIX (IMG_S * IMG_S)
#define MAXF 4096
#define Z_NEAR 0.1f
#define Z_FAR 100.0f

#define RB 32            // epilogue blocks: 32 x 256 threads x 2 px == NPIX

// ---- scratch (zero-initialized at module load; resolve restores zeros) ----
__device__ __align__(16) unsigned long long g_zbuf[NPIX];  // 0 == empty
__device__ float4 g_colors[MAXF];
__device__ int g_maxbits;             // gray max bits (idempotent across replays)
__device__ float g_slot_g2[RB];
__device__ float g_slot_gm[RB];
__device__ float g_slot_m2[RB];
__device__ float g_slot_msk[RB];
__device__ unsigned int g_ticket;

// ---------------------------------------------------------------------------
__device__ __forceinline__ float3 project_vert(float3 p,
                                               const float* __restrict__ R,
                                               const float* __restrict__ t,
                                               const float* __restrict__ K) {
    float vx = R[0] * p.x + R[1] * p.y + R[2] * p.z + t[0];
    float vy = R[3] * p.x + R[4] * p.y + R[5] * p.z + t[1];
    float vz = R[6] * p.x + R[7] * p.y + R[8] * p.z + t[2];
    float zd = vz + 1e-9f;
    float xn = vx / zd;
    float yn = vy / zd;
    float u = K[0] * xn + K[1] * yn + K[2];
    float v = K[3] * xn + K[4] * yn + K[5];
    float S = (float)IMG_S;
    float uu  = 2.0f * (u - S * 0.5f) / S;
    float vfl = S - v;
    float vvn = 2.0f * (vfl - S * 0.5f) / S;
    return make_float3(uu, vvn, vz);
}

// One warp per face: warp-uniform setup (broadcast loads, uniform control
// flow) + bbox pixel loop. Single division per pixel.
__global__ void k_raster(const float* __restrict__ verts,
                         const int*   __restrict__ faces,
                         const float* __restrict__ tex,
                         const float* __restrict__ R,
                         const float* __restrict__ t,
                         const float* __restrict__ K,
                         const float* __restrict__ Ldir,
                         const float* __restrict__ idir_p,
                         const float* __restrict__ iamb_p,
                         int F) {
    int wid  = (blockIdx.x * blockDim.x + threadIdx.x) >> 5;
    int lane = threadIdx.x & 31;
    if (wid >= F) return;
    int f = wid;

    int i0 = faces[3 * f + 0];
    int i1 = faces[3 * f + 1];
    int i2 = faces[3 * f + 2];

    float3 A = make_float3(verts[3 * i0], verts[3 * i0 + 1], verts[3 * i0 + 2]);
    float3 B = make_float3(verts[3 * i1], verts[3 * i1 + 1], verts[3 * i1 + 2]);
    float3 C = make_float3(verts[3 * i2], verts[3 * i2 + 1], verts[3 * i2 + 2]);

    // ---- lighting (world space) ----
    float3 v10 = make_float3(A.x - B.x, A.y - B.y, A.z - B.z);
    float3 v12 = make_float3(C.x - B.x, C.y - B.y, C.z - B.z);
    float nx = v10.y * v12.z - v10.z * v12.y;
    float ny = v10.z * v12.x - v10.x * v12.z;
    float nz = v10.x * v12.y - v10.y * v12.x;
    float nrm = sqrtf(nx * nx + ny * ny + nz * nz);
    float inv = 1.0f / fmaxf(nrm, 1e-5f);
    nx *= inv; ny *= inv; nz *= inv;
    float cosv = fmaxf(0.0f, nx * Ldir[0] + ny * Ldir[1] + nz * Ldir[2]);
    float light = iamb_p[0] + idir_p[0] * cosv;
    if (lane == 0) {
        g_colors[f] = make_float4(tex[3 * f + 0] * light,
                                  tex[3 * f + 1] * light,
                                  tex[3 * f + 2] * light, 0.0f);
    }

    // ---- projection (exact reference algebra) ----
    float3 p0 = project_vert(A, R, t, K);
    float3 p1 = project_vert(B, R, t, K);
    float3 p2 = project_vert(C, R, t, K);

    // per-face z reciprocals (hoists divisions out of the pixel loop)
    float rz0 = 1.0f / p0.z;
    float rz1 = 1.0f / p1.z;
    float rz2 = 1.0f / p2.z;

    // ---- bbox in pixel space ----
    float Sf = (float)IMG_S;
    float minu = fminf(fminf(p0.x, p1.x), p2.x);
    float maxu = fmaxf(fmaxf(p0.x, p1.x), p2.x);
    float minv = fminf(fminf(p0.y, p1.y), p2.y);
    float maxv = fmaxf(fmaxf(p0.y, p1.y), p2.y);
    int x0 = max(0,         (int)floorf((minu * Sf + Sf - 1.0f) * 0.5f));
    int x1 = min(IMG_S - 1, (int)ceilf ((maxu * Sf + Sf - 1.0f) * 0.5f));
    int y0 = max(0,         (int)floorf((minv * Sf + Sf - 1.0f) * 0.5f));
    int y1 = min(IMG_S - 1, (int)ceilf ((maxv * Sf + Sf - 1.0f) * 0.5f));
    if (x0 > x1 || y0 > y1) return;

    int bw = x1 - x0 + 1;
    int bh = y1 - y0 + 1;
    int total = bw * bh;

    float e0x = p2.x - p1.x, e0y = p2.y - p1.y;   // edge(v1,v2)
    float e1x = p0.x - p2.x, e1y = p0.y - p2.y;   // edge(v2,v0)
    float e2x = p1.x - p0.x, e2y = p1.y - p0.y;   // edge(v0,v1)

    for (int i = lane; i < total; i += 32) {
        int x = x0 + (i % bw);
        int y = y0 + (i / bw);
        float px = (2.0f * x + 1.0f - Sf) / Sf;
        float py = (2.0f * y + 1.0f - Sf) / Sf;

        // exact reference algebra for the sign tests
        float w0 = e0x * (py - p1.y) - e0y * (px - p1.x);
        float w1 = e1x * (py - p2.y) - e1y * (px - p2.x);
        float w2 = e2x * (py - p0.y) - e2y * (px - p0.x);
        float area = w0 + w1 + w2;
        bool ok = fabsf(area) > 1e-10f;
        bool ins = ((w0 >= 0.0f && w1 >= 0.0f && w2 >= 0.0f) ||
                    (w0 <= 0.0f && w1 <= 0.0f && w2 <= 0.0f)) && ok;
        if (!ins) continue;
        // zp = area / (w0*rz0 + w1*rz1 + w2*rz2): single division; equals
        // reference 1/(sum (w_i*ia)*rz_i + 1e-12) up to ~1ulp reassoc + 8e-12.
        float num = w0 * rz0 + w1 * rz1 + w2 * rz2;
        float zp = area / num;
        if (zp > Z_NEAR && zp < Z_FAR) {
            // inverted key: atomicMax == lexicographic min of (z_bits, f)
            // == argmin with first-index tie-break. empty == 0.
            unsigned long long key =
                ((unsigned long long)(~__float_as_uint(zp)) << 32) |
                (unsigned long long)(~(unsigned int)f);
            atomicMax(&g_zbuf[y * IMG_S + x], key);
        }
    }
}

// ---------------------------------------------------------------------------
// Single-pass fused epilogue, 2 pixels per thread (vector zbuf load; scalar
// RGB stores -- out data begins at index 1 so vector stores are misaligned).
// Loss via algebraic expansion (no maxv needed in partials).
__global__ void __launch_bounds__(256)
k_resolve_loss(float* __restrict__ out,
               const float* __restrict__ mimg,
               const float* __restrict__ mask) {
    const int tid  = threadIdx.x;
    const int lane = tid & 31;
    const int wrp  = tid >> 5;
    const int q    = blockIdx.x * 256 + tid;     // pair index; RB*256*2 == NPIX
    const int p    = q * 2;

    // ---- resolve 2 pixels ----
    ulonglong2 kk = *((const ulonglong2*)&g_zbuf[p]);
    float r0 = 0, g0 = 0, b0 = 0, r1 = 0, g1 = 0, b1 = 0;
    if (kk.x != 0ull) {
        int f = (int)(~(unsigned int)(kk.x & 0xFFFFFFFFull));
        float4 c = g_colors[f];
        r0 = c.x; g0 = c.y; b0 = c.z;
    }
    if (kk.y != 0ull) {
        int f = (int)(~(unsigned int)(kk.y & 0xFFFFFFFFull));
        float4 c = g_colors[f];
        r1 = c.x; g1 = c.y; b1 = c.z;
    }
    if ((kk.x | kk.y) != 0ull)
        *((ulonglong2*)&g_zbuf[p]) = make_ulonglong2(0ull, 0ull); // restore empty

    out[1 + 0 * NPIX + p]     = r0;
    out[1 + 0 * NPIX + p + 1] = r1;
    out[1 + 1 * NPIX + p]     = g0;
    out[1 + 1 * NPIX + p + 1] = g1;
    out[1 + 2 * NPIX + p]     = b0;
    out[1 + 2 * NPIX + p + 1] = b1;

    float gray0 = r0 + g0 + b0;
    float gray1 = r1 + g1 + b1;
    float2 mm    = *((const float2*)&mimg[p]);
    float2 kmask = *((const float2*)&mask[p]);

    // ---- block reductions: max, g^2, g*m, m^2, mask ----
    float mx = fmaxf(gray0, gray1);
    float g2 = gray0 * gray0 + gray1 * gray1;
    float gm = gray0 * mm.x + gray1 * mm.y;
    float m2 = mm.x * mm.x + mm.y * mm.y;
    float mk = kmask.x + kmask.y;
    #pragma unroll
    for (int o = 16; o > 0; o >>= 1) {
        mx = fmaxf(mx, __shfl_down_sync(0xFFFFFFFFu, mx, o));
        g2 += __shfl_down_sync(0xFFFFFFFFu, g2, o);
        gm += __shfl_down_sync(0xFFFFFFFFu, gm, o);
        m2 += __shfl_down_sync(0xFFFFFFFFu, m2, o);
        mk += __shfl_down_sync(0xFFFFFFFFu, mk, o);
    }
    __shared__ float smx[8], sg2[8], sgm[8], sm2[8], smk[8];
    if (lane == 0) { smx[wrp] = mx; sg2[wrp] = g2; sgm[wrp] = gm;
                     sm2[wrp] = m2; smk[wrp] = mk; }
    __syncthreads();
    if (tid == 0) {
        float a = smx[0], s2 = sg2[0], sm = sgm[0], s3 = sm2[0], s4 = smk[0];
        #pragma unroll
        for (int w = 1; w < 8; w++) {
            a  = fmaxf(a, smx[w]);
            s2 += sg2[w]; sm += sgm[w]; s3 += sm2[w]; s4 += smk[w];
        }
        atomicMax(&g_maxbits, __float_as_int(a));
        g_slot_g2[blockIdx.x]  = s2;
        g_slot_gm[blockIdx.x]  = sm;
        g_slot_m2[blockIdx.x]  = s3;
        g_slot_msk[blockIdx.x] = s4;
        __threadfence();
        unsigned int tkt = atomicAdd(&g_ticket, 1u);
        if (tkt == RB - 1) {
            g_ticket = 0;                        // reset for next replay
            float A = g_slot_g2[0], Bq = g_slot_gm[0];
            float C = g_slot_m2[0], M = g_slot_msk[0];
            #pragma unroll
            for (int w = 1; w < RB; w++) {
                A += g_slot_g2[w]; Bq += g_slot_gm[w];
                C += g_slot_m2[w]; M  += g_slot_msk[w];
            }
            float maxv = __int_as_float(g_maxbits);
            float S1 = A / (maxv * maxv) - 2.0f * Bq / maxv + C;
            out[0] = S1 / M;
        }
    }
}

// ---------------------------------------------------------------------------
extern "C" void kernel_launch(void* const* d_in, const int* in_sizes, int n_in,
                              void* d_out, int out_size) {
    const float* verts = (const float*)d_in[0];
    const int*   faces = (const int*)  d_in[1];
    const float* tex   = (const float*)d_in[2];
    const float* R     = (const float*)d_in[3];
    const float* t     = (const float*)d_in[4];
    const float* K     = (const float*)d_in[5];
    const float* mimg  = (const float*)d_in[6];
    const float* mask  = (const float*)d_in[7];
    const float* Ldir  = (const float*)d_in[8];
    const float* idir  = (const float*)d_in[9];
    const float* iamb  = (const float*)d_in[10];
    float* out = (float*)d_out;

    int F = in_sizes[1] / 3;

    int threads = 128;                        // 4 warps = 4 faces per block
    int blocks  = (F * 32 + threads - 1) / threads;
    k_raster<<<blocks, threads>>>(verts, faces, tex, R, t, K, Ldir, idir, iamb, F);
    k_resolve_loss<<<RB, 256>>>(out, mimg, mask);
}

// round 16
// speedup vs baseline: 2.4095x; 1.1100x over previous
#include <cuda_runtime.h>
#include <cstdint>

#define IMG_S 128
#define NPIX (IMG_S * IMG_S)
#define MAXF 4096
#define Z_NEAR 0.1f
#define Z_FAR 100.0f

#define RB 16            // epilogue blocks: 16 x 256 threads x 4 px == NPIX

// ---- scratch (zero-initialized at module load; resolve restores zeros) ----
__device__ __align__(16) unsigned long long g_zbuf[NPIX];  // 0 == empty
__device__ float4 g_colors[MAXF];
__device__ int g_maxbits;             // gray max bits (idempotent across replays)
__device__ float g_slot_g2[RB];
__device__ float g_slot_gm[RB];
__device__ float g_slot_m2[RB];
__device__ float g_slot_msk[RB];
__device__ unsigned int g_ticket;

// ---------------------------------------------------------------------------
__device__ __forceinline__ float3 project_vert(float3 p,
                                               const float* __restrict__ R,
                                               const float* __restrict__ t,
                                               const float* __restrict__ K) {
    float vx = R[0] * p.x + R[1] * p.y + R[2] * p.z + t[0];
    float vy = R[3] * p.x + R[4] * p.y + R[5] * p.z + t[1];
    float vz = R[6] * p.x + R[7] * p.y + R[8] * p.z + t[2];
    float zd = vz + 1e-9f;
    float xn = vx / zd;
    float yn = vy / zd;
    float u = K[0] * xn + K[1] * yn + K[2];
    float v = K[3] * xn + K[4] * yn + K[5];
    float S = (float)IMG_S;
    float uu  = 2.0f * (u - S * 0.5f) / S;
    float vfl = S - v;
    float vvn = 2.0f * (vfl - S * 0.5f) / S;
    return make_float3(uu, vvn, vz);
}

// One warp per face: warp-uniform setup + bbox pixel loop.
// Pixel loop uses incremental x/y stepping (no per-iteration div/mod) and a
// single FP division per pixel.
__global__ void k_raster(const float* __restrict__ verts,
                         const int*   __restrict__ faces,
                         const float* __restrict__ tex,
                         const float* __restrict__ R,
                         const float* __restrict__ t,
                         const float* __restrict__ K,
                         const float* __restrict__ Ldir,
                         const float* __restrict__ idir_p,
                         const float* __restrict__ iamb_p,
                         int F) {
    int wid  = (blockIdx.x * blockDim.x + threadIdx.x) >> 5;
    int lane = threadIdx.x & 31;
    if (wid >= F) return;
    int f = wid;

    int i0 = faces[3 * f + 0];
    int i1 = faces[3 * f + 1];
    int i2 = faces[3 * f + 2];

    float3 A = make_float3(verts[3 * i0], verts[3 * i0 + 1], verts[3 * i0 + 2]);
    float3 B = make_float3(verts[3 * i1], verts[3 * i1 + 1], verts[3 * i1 + 2]);
    float3 C = make_float3(verts[3 * i2], verts[3 * i2 + 1], verts[3 * i2 + 2]);

    // ---- lighting (world space) ----
    float3 v10 = make_float3(A.x - B.x, A.y - B.y, A.z - B.z);
    float3 v12 = make_float3(C.x - B.x, C.y - B.y, C.z - B.z);
    float nx = v10.y * v12.z - v10.z * v12.y;
    float ny = v10.z * v12.x - v10.x * v12.z;
    float nz = v10.x * v12.y - v10.y * v12.x;
    float nrm = sqrtf(nx * nx + ny * ny + nz * nz);
    float inv = 1.0f / fmaxf(nrm, 1e-5f);
    nx *= inv; ny *= inv; nz *= inv;
    float cosv = fmaxf(0.0f, nx * Ldir[0] + ny * Ldir[1] + nz * Ldir[2]);
    float light = iamb_p[0] + idir_p[0] * cosv;
    if (lane == 0) {
        g_colors[f] = make_float4(tex[3 * f + 0] * light,
                                  tex[3 * f + 1] * light,
                                  tex[3 * f + 2] * light, 0.0f);
    }

    // ---- projection (exact reference algebra) ----
    float3 p0 = project_vert(A, R, t, K);
    float3 p1 = project_vert(B, R, t, K);
    float3 p2 = project_vert(C, R, t, K);

    // per-face z reciprocals (hoists divisions out of the pixel loop)
    float rz0 = 1.0f / p0.z;
    float rz1 = 1.0f / p1.z;
    float rz2 = 1.0f / p2.z;

    // ---- bbox in pixel space ----
    float Sf = (float)IMG_S;
    float minu = fminf(fminf(p0.x, p1.x), p2.x);
    float maxu = fmaxf(fmaxf(p0.x, p1.x), p2.x);
    float minv = fminf(fminf(p0.y, p1.y), p2.y);
    float maxv = fmaxf(fmaxf(p0.y, p1.y), p2.y);
    int x0 = max(0,         (int)floorf((minu * Sf + Sf - 1.0f) * 0.5f));
    int x1 = min(IMG_S - 1, (int)ceilf ((maxu * Sf + Sf - 1.0f) * 0.5f));
    int y0 = max(0,         (int)floorf((minv * Sf + Sf - 1.0f) * 0.5f));
    int y1 = min(IMG_S - 1, (int)ceilf ((maxv * Sf + Sf - 1.0f) * 0.5f));
    if (x0 > x1 || y0 > y1) return;

    int bw = x1 - x0 + 1;
    int bh = y1 - y0 + 1;

    float e0x = p2.x - p1.x, e0y = p2.y - p1.y;   // edge(v1,v2)
    float e1x = p0.x - p2.x, e1y = p0.y - p2.y;   // edge(v2,v0)
    float e2x = p1.x - p0.x, e2y = p1.y - p0.y;   // edge(v0,v1)

    // incremental stepping: i = yy*bw + xr walks lane, lane+32, ...
    // q32/r32 are warp-uniform; the lane div/mod happens exactly once.
    int q32 = 32 / bw;
    int r32 = 32 - q32 * bw;
    int xr  = lane % bw;
    int yy  = lane / bw;

    while (yy < bh) {
        int x = x0 + xr;
        int y = y0 + yy;
        float px = (2.0f * x + 1.0f - Sf) / Sf;
        float py = (2.0f * y + 1.0f - Sf) / Sf;

        // exact reference algebra for the sign tests
        float w0 = e0x * (py - p1.y) - e0y * (px - p1.x);
        float w1 = e1x * (py - p2.y) - e1y * (px - p2.x);
        float w2 = e2x * (py - p0.y) - e2y * (px - p0.x);
        float area = w0 + w1 + w2;
        bool ok = fabsf(area) > 1e-10f;
        bool ins = ((w0 >= 0.0f && w1 >= 0.0f && w2 >= 0.0f) ||
                    (w0 <= 0.0f && w1 <= 0.0f && w2 <= 0.0f)) && ok;
        if (ins) {
            // zp = area / (w0*rz0 + w1*rz1 + w2*rz2): single division; equals
            // reference 1/(sum (w_i*ia)*rz_i + 1e-12) up to ~1ulp + 8e-12.
            float num = w0 * rz0 + w1 * rz1 + w2 * rz2;
            float zp = area / num;
            if (zp > Z_NEAR && zp < Z_FAR) {
                // inverted key: atomicMax == lexicographic min of (z_bits, f)
                // == argmin with first-index tie-break. empty == 0.
                unsigned long long key =
                    ((unsigned long long)(~__float_as_uint(zp)) << 32) |
                    (unsigned long long)(~(unsigned int)f);
                atomicMax(&g_zbuf[y * IMG_S + x], key);
            }
        }
        xr += r32;
        yy += q32;
        if (xr >= bw) { xr -= bw; yy += 1; }
    }
}

// ---------------------------------------------------------------------------
// Single-pass fused epilogue, 4 pixels per thread (2x vector zbuf loads +
// float4 mimg/mask; scalar RGB stores since out data begins at index 1).
// Loss via algebraic expansion (no maxv needed in partials).
__global__ void __launch_bounds__(256)
k_resolve_loss(float* __restrict__ out,
               const float* __restrict__ mimg,
               const float* __restrict__ mask) {
    const int tid  = threadIdx.x;
    const int lane = tid & 31;
    const int wrp  = tid >> 5;
    const int q    = blockIdx.x * 256 + tid;     // quad index; RB*256*4 == NPIX
    const int p    = q * 4;

    // ---- resolve 4 pixels (independent chains, all loads issued up front) --
    ulonglong2 kA = *((const ulonglong2*)&g_zbuf[p]);
    ulonglong2 kB = *((const ulonglong2*)&g_zbuf[p + 2]);
    float4 mm     = *((const float4*)&mimg[p]);
    float4 kmask  = *((const float4*)&mask[p]);

    float rr[4] = {0, 0, 0, 0}, gg[4] = {0, 0, 0, 0}, bb[4] = {0, 0, 0, 0};
    unsigned long long kv[4] = {kA.x, kA.y, kB.x, kB.y};
    #pragma unroll
    for (int j = 0; j < 4; j++) {
        if (kv[j] != 0ull) {
            int f = (int)(~(unsigned int)(kv[j] & 0xFFFFFFFFull));
            float4 c = g_colors[f];
            rr[j] = c.x; gg[j] = c.y; bb[j] = c.z;
        }
    }
    if ((kv[0] | kv[1] | kv[2] | kv[3]) != 0ull) {
        *((ulonglong2*)&g_zbuf[p])     = make_ulonglong2(0ull, 0ull);
        *((ulonglong2*)&g_zbuf[p + 2]) = make_ulonglong2(0ull, 0ull);
    }

    #pragma unroll
    for (int j = 0; j < 4; j++) {
        out[1 + 0 * NPIX + p + j] = rr[j];
        out[1 + 1 * NPIX + p + j] = gg[j];
        out[1 + 2 * NPIX + p + j] = bb[j];
    }

    float gray[4];
    #pragma unroll
    for (int j = 0; j < 4; j++) gray[j] = rr[j] + gg[j] + bb[j];
    float mv[4] = {mm.x, mm.y, mm.z, mm.w};
    float kv4[4] = {kmask.x, kmask.y, kmask.z, kmask.w};

    // ---- block reductions: max, g^2, g*m, m^2, mask ----
    float mx = fmaxf(fmaxf(gray[0], gray[1]), fmaxf(gray[2], gray[3]));
    float g2 = 0, gm = 0, m2 = 0, mk = 0;
    #pragma unroll
    for (int j = 0; j < 4; j++) {
        g2 += gray[j] * gray[j];
        gm += gray[j] * mv[j];
        m2 += mv[j] * mv[j];
        mk += kv4[j];
    }
    #pragma unroll
    for (int o = 16; o > 0; o >>= 1) {
        mx = fmaxf(mx, __shfl_down_sync(0xFFFFFFFFu, mx, o));
        g2 += __shfl_down_sync(0xFFFFFFFFu, g2, o);
        gm += __shfl_down_sync(0xFFFFFFFFu, gm, o);
        m2 += __shfl_down_sync(0xFFFFFFFFu, m2, o);
        mk += __shfl_down_sync(0xFFFFFFFFu, mk, o);
    }
    __shared__ float smx[8], sg2[8], sgm[8], sm2[8], smk[8];
    if (lane == 0) { smx[wrp] = mx; sg2[wrp] = g2; sgm[wrp] = gm;
                     sm2[wrp] = m2; smk[wrp] = mk; }
    __syncthreads();
    if (tid == 0) {
        float a = smx[0], s2 = sg2[0], sm = sgm[0], s3 = sm2[0], s4 = smk[0];
        #pragma unroll
        for (int w = 1; w < 8; w++) {
            a  = fmaxf(a, smx[w]);
            s2 += sg2[w]; sm += sgm[w]; s3 += sm2[w]; s4 += smk[w];
        }
        atomicMax(&g_maxbits, __float_as_int(a));
        g_slot_g2[blockIdx.x]  = s2;
        g_slot_gm[blockIdx.x]  = sm;
        g_slot_m2[blockIdx.x]  = s3;
        g_slot_msk[blockIdx.x] = s4;
        __threadfence();
        unsigned int tkt = atomicAdd(&g_ticket, 1u);
        if (tkt == RB - 1) {
            g_ticket = 0;                        // reset for next replay
            float A = g_slot_g2[0], Bq = g_slot_gm[0];
            float C = g_slot_m2[0], M = g_slot_msk[0];
            #pragma unroll
            for (int w = 1; w < RB; w++) {
                A += g_slot_g2[w]; Bq += g_slot_gm[w];
                C += g_slot_m2[w]; M  += g_slot_msk[w];
            }
            float maxv = __int_as_float(g_maxbits);
            float S1 = A / (maxv * maxv) - 2.0f * Bq / maxv + C;
            out[0] = S1 / M;
        }
    }
}

// ---------------------------------------------------------------------------
extern "C" void kernel_launch(void* const* d_in, const int* in_sizes, int n_in,
                              void* d_out, int out_size) {
    const float* verts = (const float*)d_in[0];
    const int*   faces = (const int*)  d_in[1];
    const float* tex   = (const float*)d_in[2];
    const float* R     = (const float*)d_in[3];
    const float* t     = (const float*)d_in[4];
    const float* K     = (const float*)d_in[5];
    const float* mimg  = (const float*)d_in[6];
    const float* mask  = (const float*)d_in[7];
    const float* Ldir  = (const float*)d_in[8];
    const float* idir  = (const float*)d_in[9];
    const float* iamb  = (const float*)d_in[10];
    float* out = (float*)d_out;

    int F = in_sizes[1] / 3;

    int threads = 128;                        // 4 warps = 4 faces per block
    int blocks  = (F * 32 + threads - 1) / threads;
    k_raster<<<blocks, threads>>>(verts, faces, tex, R, t, K, Ldir, idir, iamb, F);
    k_resolve_loss<<<RB, 256>>>(out, mimg, mask);
}